// round 11
// baseline (speedup 1.0000x reference)
#include <cuda_runtime.h>
#include <math.h>
#include <stdint.h>

#define NB 2
#define SL 2048
#define HDIM 2048
#define NHEAD 16
#define HD 128
#define MTOT (NB*SL)          // 4096
#define N3H (3*HDIM)          // 6144

#define CLIPV 8.0f
#define SM_SCALE 0.08838834764831845f   // 1/sqrt(128)

// ---- scratch (device globals; no allocation allowed) ----
__device__ uint32_t g_hid_p[(size_t)MTOT*HDIM];    // hidden, tf32 bits, k-perm
__device__ uint32_t g_wqkv_p[(size_t)N3H*HDIM];    // Wqkv,  tf32 bits, k-perm
__device__ uint32_t g_wout_p[(size_t)HDIM*HDIM];   // Wout,  tf32 bits, k-perm
__device__ uint32_t g_q[(size_t)NB*NHEAD*SL*HD];   // [B,NH,S,d-slot], pre-scaled
__device__ uint32_t g_k[(size_t)NB*NHEAD*SL*HD];   // [B,NH,S,d-slot]
__device__ uint32_t g_vT[(size_t)NB*NHEAD*HD*SL];  // [B,NH,d-slot,s-keyperm]
__device__ uint32_t g_ctx[(size_t)MTOT*HDIM];      // tf32 bits, k-perm

__device__ __forceinline__ uint32_t f2tf32(float x) {
    uint32_t r;
    asm("cvt.rna.tf32.f32 %0, %1;" : "=r"(r) : "f"(x));
    return r;
}
__device__ __forceinline__ void mma16n8k8(float* d, const uint32_t* a,
                                          const uint32_t* b) {
    asm volatile(
        "mma.sync.aligned.m16n8k8.row.col.f32.tf32.tf32.f32 "
        "{%0,%1,%2,%3}, {%4,%5,%6,%7}, {%8,%9}, {%0,%1,%2,%3};"
        : "+f"(d[0]), "+f"(d[1]), "+f"(d[2]), "+f"(d[3])
        : "r"(a[0]), "r"(a[1]), "r"(a[2]), "r"(a[3]),
          "r"(b[0]), "r"(b[1]));
}
__device__ __forceinline__ void cp16(uint32_t dst, const void* src) {
    asm volatile("cp.async.ca.shared.global [%0], [%1], 16;"
                 :: "r"(dst), "l"(src));
}
#define CP_COMMIT() asm volatile("cp.async.commit_group;")
#define CP_WAIT0()  asm volatile("cp.async.wait_group 0;")
#define CP_WAIT1()  asm volatile("cp.async.wait_group 1;")

__device__ __forceinline__ uint32_t smem_u32(const void* p) {
    uint32_t a;
    asm("{ .reg .u64 t; cvta.to.shared.u64 t, %1; cvt.u32.u64 %0, t; }"
        : "=r"(a) : "l"(p));
    return a;
}

// within-8 pair permutation: slot = (k&3)*2 + ((k&7)>>2)
__device__ __forceinline__ int perm8(int k) {
    return (k & ~7) | ((k & 3) << 1) | ((k & 7) >> 2);
}

// ============================================================================
// prep: out[row][perm8(col)] = tf32(in[row][col])
// ============================================================================
__global__ void prep_perm(const float* __restrict__ in,
                          uint32_t* __restrict__ out, int n4)
{
    int t = blockIdx.x*256 + threadIdx.x;
    if (t >= n4) return;
    int idx = t*4;
    float4 v = *(const float4*)(in + idx);
    int base = idx & ~7;
    int h = (idx >> 2) & 1;
    out[base + 0 + h] = f2tf32(v.x);
    out[base + 2 + h] = f2tf32(v.y);
    out[base + 4 + h] = f2tf32(v.z);
    out[base + 6 + h] = f2tf32(v.w);
}

// ============================================================================
// tf32 NT GEMM (mma.sync) — exact R6 config: 128x128x32, 8 warps (wm4 x wn2),
// cp.async 2-stage, launch_bounds(256,2).
// MODE 0: plain fp32 store. MODE 1: clamp, scale(Q), tf32, scatter
//   Q/K -> [B,NH,S,d-slot];  V -> g_vT [B,NH,d-slot,s-keyperm].
// ============================================================================
#define GSTG 10240          // words per stage (As 5120 + Bs 5120)
#define GEMM_SMEM_BYTES (2*GSTG*4)

template<int MODE>
__global__ __launch_bounds__(256, 2)
void mma_gemm_p(const uint32_t* __restrict__ A, const uint32_t* __restrict__ Bm,
                float* __restrict__ C, int Ndim, int Kdim)
{
    extern __shared__ uint32_t gsm[];
    const int tid  = threadIdx.x;
    const int lane = tid & 31;
    const int grp  = lane >> 2;
    const int tig  = lane & 3;
    const int wm   = (tid >> 5) & 3;
    const int wn   = tid >> 7;

    const int k4 = (tid & 7) * 4;
    const int mb = tid >> 3;

    const uint32_t* Ag = A  + (size_t)(blockIdx.y*128 + mb)*Kdim + k4;
    const uint32_t* Bg = Bm + (size_t)(blockIdx.x*128 + mb)*Kdim + k4;
    const uint32_t sbase = smem_u32(gsm);

    float acc[2][8][4];
#pragma unroll
    for (int mt = 0; mt < 2; mt++)
#pragma unroll
        for (int nt = 0; nt < 8; nt++)
#pragma unroll
            for (int r = 0; r < 4; r++) acc[mt][nt][r] = 0.f;

    const int NC = Kdim / 32;

    {
        uint32_t da = sbase + (mb*40 + k4)*4;
        uint32_t db = da + 5120*4;
#pragma unroll
        for (int i = 0; i < 4; i++) {
            cp16(da + i*32*40*4, Ag + (size_t)i*32*Kdim);
            cp16(db + i*32*40*4, Bg + (size_t)i*32*Kdim);
        }
        CP_COMMIT();
    }

    for (int c = 0; c < NC; c++) {
        const int st = c & 1;
        if (c + 1 < NC) {
            uint32_t da = sbase + ((st^1)*GSTG + mb*40 + k4)*4;
            uint32_t db = da + 5120*4;
            const int kt = (c+1)*32;
#pragma unroll
            for (int i = 0; i < 4; i++) {
                cp16(da + i*32*40*4, Ag + kt + (size_t)i*32*Kdim);
                cp16(db + i*32*40*4, Bg + kt + (size_t)i*32*Kdim);
            }
            CP_COMMIT();
            CP_WAIT1();
        } else {
            CP_WAIT0();
        }
        __syncthreads();

        const uint32_t* As = gsm + st*GSTG;
        const uint32_t* Bs = As + 5120;
#pragma unroll
        for (int kk = 0; kk < 4; kk++) {
            uint32_t af[2][4];
#pragma unroll
            for (int mt = 0; mt < 2; mt++) {
                const int r = wm*32 + mt*16 + grp;
                uint2 a0 = *(const uint2*)&As[r*40     + kk*8 + 2*tig];
                uint2 a1 = *(const uint2*)&As[(r+8)*40 + kk*8 + 2*tig];
                af[mt][0] = a0.x; af[mt][1] = a1.x;
                af[mt][2] = a0.y; af[mt][3] = a1.y;
            }
#pragma unroll
            for (int nt = 0; nt < 8; nt++) {
                const int r = wn*64 + nt*8 + grp;
                uint2 b = *(const uint2*)&Bs[r*40 + kk*8 + 2*tig];
                uint32_t bf[2] = {b.x, b.y};
                mma16n8k8(acc[0][nt], af[0], bf);
                mma16n8k8(acc[1][nt], af[1], bf);
            }
        }
        __syncthreads();
    }

    if (MODE == 0) {
#pragma unroll
        for (int mt = 0; mt < 2; mt++) {
            const int r0 = blockIdx.y*128 + wm*32 + mt*16 + grp;
#pragma unroll
            for (int nt = 0; nt < 8; nt++) {
                const int n = blockIdx.x*128 + wn*64 + nt*8 + 2*tig;
                *(float2*)(C + (size_t)r0*Ndim + n) =
                    make_float2(acc[mt][nt][0], acc[mt][nt][1]);
                *(float2*)(C + (size_t)(r0+8)*Ndim + n) =
                    make_float2(acc[mt][nt][2], acc[mt][nt][3]);
            }
        }
    } else {
        const int nblk = blockIdx.x*128;
        const int part = nblk >> 11;            // 0:Q 1:K 2:V
        const int hh   = (nblk & 2047) >> 7;
        if (part < 2) {
            uint32_t* base = (part == 0) ? g_q : g_k;
            const float sc = (part == 0) ? SM_SCALE : 1.0f;
#pragma unroll
            for (int mt = 0; mt < 2; mt++) {
#pragma unroll
                for (int rr = 0; rr < 2; rr++) {
                    const int m  = blockIdx.y*128 + wm*32 + mt*16 + grp + rr*8;
                    const int bb = m >> 11;
                    const int ss = m & 2047;
                    uint32_t* row = base + ((((size_t)bb*NHEAD) + hh)*SL + ss)*HD;
#pragma unroll
                    for (int nt = 0; nt < 8; nt++) {
                        const int d = wn*64 + nt*8 + 2*tig;
                        float v0 = fminf(fmaxf(acc[mt][nt][rr*2+0], -CLIPV), CLIPV)*sc;
                        float v1 = fminf(fmaxf(acc[mt][nt][rr*2+1], -CLIPV), CLIPV)*sc;
                        row[perm8(d)]   = f2tf32(v0);
                        row[perm8(d+1)] = f2tf32(v1);
                    }
                }
            }
        } else {
#pragma unroll
            for (int mt = 0; mt < 2; mt++) {
#pragma unroll
                for (int rr = 0; rr < 2; rr++) {
                    const int m  = blockIdx.y*128 + wm*32 + mt*16 + grp + rr*8;
                    const int bb = m >> 11;
                    const int ss = m & 2047;
                    const int scol = perm8(ss);
                    uint32_t* vb = g_vT + (((size_t)bb*NHEAD + hh)*HD)*SL + scol;
#pragma unroll
                    for (int nt = 0; nt < 8; nt++) {
                        const int d = wn*64 + nt*8 + 2*tig;
                        float v0 = fminf(fmaxf(acc[mt][nt][rr*2+0], -CLIPV), CLIPV);
                        float v1 = fminf(fmaxf(acc[mt][nt][rr*2+1], -CLIPV), CLIPV);
                        vb[(size_t)perm8(d)  *SL] = f2tf32(v0);
                        vb[(size_t)perm8(d+1)*SL] = f2tf32(v1);
                    }
                }
            }
        }
    }
}

// ============================================================================
// Tensor-core flash attention v5: occupancy 2. Single-buffered K/V/bias
// (104 KB smem), Q fragments streamed from gmem (L1-resident), P in regs,
// heavy-qb-first. launch_bounds(256,2) — cross-CTA overlap hides the
// blocking tile loads and softmax chains.
// ============================================================================
#define KSTR 136
#define VSTR 72
#define BSTR 68
#define KS_SZ (64*KSTR)
#define VT_SZ (128*VSTR)
#define BS_SZ (128*BSTR)
#define ATT_U32 (KS_SZ + VT_SZ + BS_SZ)
#define ATT_BYTES (ATT_U32*4)        // 106,496 B

__global__ __launch_bounds__(256, 2)
void attn_mma(const float* __restrict__ bias)
{
    extern __shared__ uint32_t sm[];
    uint32_t* Ks = sm;                          // [64][KSTR]
    uint32_t* Vt = sm + KS_SZ;                  // [128][VSTR]
    float*    Bt = (float*)(sm + KS_SZ + VT_SZ);// [128][BSTR]
    const uint32_t sKs = smem_u32(Ks);
    const uint32_t sVt = smem_u32(Vt);
    const uint32_t sBs = smem_u32(Bt);

    const int qb = (int)gridDim.x - 1 - (int)blockIdx.x;   // heavy first
    const int hh = blockIdx.y;
    const int bb = blockIdx.z;
    const int tid  = threadIdx.x;
    const int w    = tid >> 5;
    const int lane = tid & 31;
    const int grp  = lane >> 2;
    const int tig  = lane & 3;
    const int rbase = w*16;

    const size_t bhs = ((size_t)bb*NHEAD + hh)*SL;
    const uint32_t* Qg = g_q + (bhs + (size_t)qb*128)*HD;
    const uint32_t* Kg = g_k + bhs*HD;
    const uint32_t* Vg = g_vT + bhs*HD;
    const float* biasg = bias + ((size_t)hh*SL + (size_t)qb*128)*SL;

    // per-thread Q row base (fragments streamed per tile; L1-hot)
    const uint32_t* q0 = Qg + (size_t)(rbase + grp)*HD + 2*tig;
    const uint32_t* q1 = q0 + 8*HD;

    float o[16][4];
#pragma unroll
    for (int nt = 0; nt < 16; nt++)
#pragma unroll
        for (int r = 0; r < 4; r++) o[nt][r] = 0.f;
    float mr0 = -INFINITY, mr1 = -INFINITY, lr0 = 0.f, lr1 = 0.f;

    const int rg0 = qb*128 + rbase + grp;
    const int warp_rmax = qb*128 + rbase + 15;
    const int kb_max = 2*qb + 1;

    for (int kb = 0; kb <= kb_max; kb++) {
        // ---- blocking tile load (occ-2 partner CTA hides this) ----
        {
            const uint32_t* Kt = Kg + (size_t)kb*64*HD;
#pragma unroll
            for (int p = 0; p < 8; p++) {
                int i = tid + p*256;
                int r = i >> 5, c4 = (i & 31) << 2;
                cp16(sKs + (perm8(r)*KSTR + c4)*4, Kt + (size_t)r*HD + c4);
            }
            const uint32_t* Vt0 = Vg + (size_t)kb*64;
#pragma unroll
            for (int p = 0; p < 8; p++) {
                int i = tid + p*256;
                int d = i >> 4, c4 = (i & 15) << 2;
                cp16(sVt + (d*VSTR + c4)*4, Vt0 + (size_t)d*SL + c4);
            }
            const float* Bg0 = biasg + kb*64;
#pragma unroll
            for (int p = 0; p < 8; p++) {
                int i = tid + p*256;
                int r = i >> 4, c4 = (i & 15) << 2;
                cp16(sBs + (r*BSTR + c4)*4, Bg0 + (size_t)r*SL + c4);
            }
        }
        CP_COMMIT();
        CP_WAIT0();
        __syncthreads();

        if (kb*64 <= warp_rmax) {
            // ---- QK^T: m16 x n64, k=128 (Q streamed from gmem/L1) ----
            float c[8][4];
#pragma unroll
            for (int nt = 0; nt < 8; nt++)
#pragma unroll
                for (int r = 0; r < 4; r++) c[nt][r] = 0.f;

#pragma unroll
            for (int kk = 0; kk < 16; kk++) {
                uint2 qa = *(const uint2*)(q0 + kk*8);
                uint2 qb2 = *(const uint2*)(q1 + kk*8);
                uint32_t af[4] = {qa.x, qb2.x, qa.y, qb2.y};
#pragma unroll
                for (int nt = 0; nt < 8; nt++) {
                    uint2 kf = *(const uint2*)&Ks[(nt*8+grp)*KSTR + kk*8 + 2*tig];
                    uint32_t bf[2] = {kf.x, kf.y};
                    mma16n8k8(c[nt], af, bf);
                }
            }

            // ---- bias (smem) + causal + online softmax ----
            const float* b0r = Bt + (rbase+grp)*BSTR;
            const float* b1r = b0r + 8*BSTR;
            float rm0 = -INFINITY, rm1 = -INFINITY;
#pragma unroll
            for (int nt = 0; nt < 8; nt++) {
                const int k0 = nt*8 + tig;
                const int cg = kb*64 + k0;
                c[nt][0] = (cg     > rg0    ) ? -INFINITY : c[nt][0] + b0r[k0];
                c[nt][1] = (cg + 4 > rg0    ) ? -INFINITY : c[nt][1] + b0r[k0+4];
                c[nt][2] = (cg     > rg0 + 8) ? -INFINITY : c[nt][2] + b1r[k0];
                c[nt][3] = (cg + 4 > rg0 + 8) ? -INFINITY : c[nt][3] + b1r[k0+4];
                rm0 = fmaxf(rm0, fmaxf(c[nt][0], c[nt][1]));
                rm1 = fmaxf(rm1, fmaxf(c[nt][2], c[nt][3]));
            }
            rm0 = fmaxf(rm0, __shfl_xor_sync(0xffffffffu, rm0, 1));
            rm0 = fmaxf(rm0, __shfl_xor_sync(0xffffffffu, rm0, 2));
            rm1 = fmaxf(rm1, __shfl_xor_sync(0xffffffffu, rm1, 1));
            rm1 = fmaxf(rm1, __shfl_xor_sync(0xffffffffu, rm1, 2));

            const float mn0 = fmaxf(mr0, rm0);
            const float mn1 = fmaxf(mr1, rm1);
            const float corr0 = __expf(mr0 - mn0);
            const float corr1 = __expf(mr1 - mn1);
            mr0 = mn0; mr1 = mn1;

            float rs0 = 0.f, rs1 = 0.f;
#pragma unroll
            for (int nt = 0; nt < 8; nt++) {
                c[nt][0] = __uint_as_float(f2tf32(__expf(c[nt][0] - mn0)));
                c[nt][1] = __uint_as_float(f2tf32(__expf(c[nt][1] - mn0)));
                c[nt][2] = __uint_as_float(f2tf32(__expf(c[nt][2] - mn1)));
                c[nt][3] = __uint_as_float(f2tf32(__expf(c[nt][3] - mn1)));
                rs0 += c[nt][0] + c[nt][1];
                rs1 += c[nt][2] + c[nt][3];
            }
            rs0 += __shfl_xor_sync(0xffffffffu, rs0, 1);
            rs0 += __shfl_xor_sync(0xffffffffu, rs0, 2);
            rs1 += __shfl_xor_sync(0xffffffffu, rs1, 1);
            rs1 += __shfl_xor_sync(0xffffffffu, rs1, 2);
            lr0 = lr0*corr0 + rs0;
            lr1 = lr1*corr1 + rs1;
#pragma unroll
            for (int nt = 0; nt < 16; nt++) {
                o[nt][0] *= corr0; o[nt][1] *= corr0;
                o[nt][2] *= corr1; o[nt][3] *= corr1;
            }

            // ---- P V: m16 x n128, k=64; A-fragment direct from C-fragment ----
#pragma unroll
            for (int kk = 0; kk < 8; kk++) {
                uint32_t af[4] = {__float_as_uint(c[kk][0]),
                                  __float_as_uint(c[kk][2]),
                                  __float_as_uint(c[kk][1]),
                                  __float_as_uint(c[kk][3])};
#pragma unroll
                for (int nt = 0; nt < 16; nt++) {
                    uint2 vb = *(const uint2*)&Vt[(nt*8+grp)*VSTR + kk*8 + 2*tig];
                    uint32_t bf[2] = {vb.x, vb.y};
                    mma16n8k8(o[nt], af, bf);
                }
            }
        }

        __syncthreads();          // all reads done before next tile overwrites
    }

    // epilogue: normalize, tf32, write ctx (slot order matches g_wout_p perm)
    const float inv0 = 1.0f / lr0;
    const float inv1 = 1.0f / lr1;
    uint32_t* dst0 = g_ctx + ((size_t)bb*SL + rg0    )*HDIM + hh*HD;
    uint32_t* dst1 = g_ctx + ((size_t)bb*SL + rg0 + 8)*HDIM + hh*HD;
#pragma unroll
    for (int nt = 0; nt < 16; nt++) {
        const int d = nt*8 + 2*tig;
        *(uint2*)(dst0 + d) = make_uint2(f2tf32(o[nt][0]*inv0),
                                         f2tf32(o[nt][1]*inv0));
        *(uint2*)(dst1 + d) = make_uint2(f2tf32(o[nt][2]*inv1),
                                         f2tf32(o[nt][3]*inv1));
    }
}

// ============================================================================
extern "C" void kernel_launch(void* const* d_in, const int* in_sizes, int n_in,
                              void* d_out, int out_size)
{
    const float* hidden = (const float*)d_in[0];   // [B,S,H]
    const float* bias   = (const float*)d_in[1];   // [NH,S,S]
    // d_in[2] attention_mask: deterministic causal, applied analytically
    const float* Wqkv   = (const float*)d_in[3];   // [3H,H]
    const float* Wout   = (const float*)d_in[4];   // [H,H]
    float* out = (float*)d_out;

    cudaFuncSetAttribute(attn_mma,
                         cudaFuncAttributeMaxDynamicSharedMemorySize, ATT_BYTES);
    cudaFuncSetAttribute(mma_gemm_p<0>,
                         cudaFuncAttributeMaxDynamicSharedMemorySize, GEMM_SMEM_BYTES);
    cudaFuncSetAttribute(mma_gemm_p<1>,
                         cudaFuncAttributeMaxDynamicSharedMemorySize, GEMM_SMEM_BYTES);

    void *hidp, *wqkvp, *woutp, *ctxp;
    cudaGetSymbolAddress(&hidp,  g_hid_p);
    cudaGetSymbolAddress(&wqkvp, g_wqkv_p);
    cudaGetSymbolAddress(&woutp, g_wout_p);
    cudaGetSymbolAddress(&ctxp,  g_ctx);

    // 0) permute + tf32-convert inputs
    prep_perm<<<(MTOT*HDIM/4 + 255)/256, 256>>>(hidden, (uint32_t*)hidp, MTOT*HDIM/4);
    prep_perm<<<(N3H*HDIM/4  + 255)/256, 256>>>(Wqkv,   (uint32_t*)wqkvp, N3H*HDIM/4);
    prep_perm<<<(HDIM*HDIM/4 + 255)/256, 256>>>(Wout,   (uint32_t*)woutp, HDIM*HDIM/4);

    // 1) QKV projection + clamp + scale(Q) + scatter (V transposed)
    mma_gemm_p<1><<<dim3(N3H/128, MTOT/128), 256, GEMM_SMEM_BYTES>>>(
        (const uint32_t*)hidp, (const uint32_t*)wqkvp, nullptr, N3H, HDIM);

    // 2) attention (occ-2, single-buffered tiles, Q streamed, P in regs)
    attn_mma<<<dim3(SL/128, NHEAD, NB), 256, ATT_BYTES>>>(bias);

    // 3) output projection
    mma_gemm_p<0><<<dim3(HDIM/128, MTOT/128), 256, GEMM_SMEM_BYTES>>>(
        (const uint32_t*)ctxp, (const uint32_t*)woutp, out, HDIM, HDIM);
}

// round 12
// speedup vs baseline: 1.0975x; 1.0975x over previous
#include <cuda_runtime.h>
#include <math.h>
#include <stdint.h>

#define NB 2
#define SL 2048
#define HDIM 2048
#define NHEAD 16
#define HD 128
#define MTOT (NB*SL)          // 4096
#define N3H (3*HDIM)          // 6144

#define CLIPV 8.0f
#define SM_SCALE 0.08838834764831845f   // 1/sqrt(128)

// ---- scratch (device globals; no allocation allowed) ----
__device__ uint32_t g_hid_p[(size_t)MTOT*HDIM];    // hidden, tf32 bits, k-perm
__device__ uint32_t g_wqkv_p[(size_t)N3H*HDIM];    // Wqkv,  tf32 bits, k-perm
__device__ uint32_t g_wout_p[(size_t)HDIM*HDIM];   // Wout,  tf32 bits, k-perm
__device__ uint32_t g_q[(size_t)NB*NHEAD*SL*HD];   // [B,NH,S,d-slot], pre-scaled
__device__ uint32_t g_k[(size_t)NB*NHEAD*SL*HD];   // [B,NH,S,d-slot]
__device__ uint32_t g_vT[(size_t)NB*NHEAD*HD*SL];  // [B,NH,d-slot,s-keyperm]
__device__ uint32_t g_ctx[(size_t)MTOT*HDIM];      // tf32 bits, k-perm

__device__ __forceinline__ uint32_t f2tf32(float x) {
    uint32_t r;
    asm("cvt.rna.tf32.f32 %0, %1;" : "=r"(r) : "f"(x));
    return r;
}
__device__ __forceinline__ void mma16n8k8(float* d, const uint32_t* a,
                                          const uint32_t* b) {
    asm volatile(
        "mma.sync.aligned.m16n8k8.row.col.f32.tf32.tf32.f32 "
        "{%0,%1,%2,%3}, {%4,%5,%6,%7}, {%8,%9}, {%0,%1,%2,%3};"
        : "+f"(d[0]), "+f"(d[1]), "+f"(d[2]), "+f"(d[3])
        : "r"(a[0]), "r"(a[1]), "r"(a[2]), "r"(a[3]),
          "r"(b[0]), "r"(b[1]));
}
__device__ __forceinline__ void cp16(uint32_t dst, const void* src) {
    asm volatile("cp.async.ca.shared.global [%0], [%1], 16;"
                 :: "r"(dst), "l"(src));
}
#define CP_COMMIT() asm volatile("cp.async.commit_group;")
#define CP_WAIT0()  asm volatile("cp.async.wait_group 0;")
#define CP_WAIT1()  asm volatile("cp.async.wait_group 1;")

__device__ __forceinline__ uint32_t smem_u32(const void* p) {
    uint32_t a;
    asm("{ .reg .u64 t; cvta.to.shared.u64 t, %1; cvt.u32.u64 %0, t; }"
        : "=r"(a) : "l"(p));
    return a;
}

// within-8 pair permutation: slot = (k&3)*2 + ((k&7)>>2)
__device__ __forceinline__ int perm8(int k) {
    return (k & ~7) | ((k & 3) << 1) | ((k & 7) >> 2);
}

// ============================================================================
// prep: out[row][perm8(col)] = tf32(in[row][col])
// ============================================================================
__global__ void prep_perm(const float* __restrict__ in,
                          uint32_t* __restrict__ out, int n4)
{
    int t = blockIdx.x*256 + threadIdx.x;
    if (t >= n4) return;
    int idx = t*4;
    float4 v = *(const float4*)(in + idx);
    int base = idx & ~7;
    int h = (idx >> 2) & 1;
    out[base + 0 + h] = f2tf32(v.x);
    out[base + 2 + h] = f2tf32(v.y);
    out[base + 4 + h] = f2tf32(v.z);
    out[base + 6 + h] = f2tf32(v.w);
}

// ============================================================================
// tf32 NT GEMM (mma.sync) — proven R6 config: 128x128x32, 8 warps (wm4 x wn2),
// cp.async 2-stage, launch_bounds(256,2), kk-loop fragment loads.
// MODE 0: plain fp32 store. MODE 1: clamp, scale(Q), tf32, scatter
//   Q/K -> [B,NH,S,d-slot];  V -> g_vT [B,NH,d-slot,s-keyperm].
// ============================================================================
#define GSTG 10240          // words per stage (As 5120 + Bs 5120)
#define GEMM_SMEM_BYTES (2*GSTG*4)

template<int MODE>
__global__ __launch_bounds__(256, 2)
void mma_gemm_p(const uint32_t* __restrict__ A, const uint32_t* __restrict__ Bm,
                float* __restrict__ C, int Ndim, int Kdim)
{
    extern __shared__ uint32_t gsm[];
    const int tid  = threadIdx.x;
    const int lane = tid & 31;
    const int grp  = lane >> 2;
    const int tig  = lane & 3;
    const int wm   = (tid >> 5) & 3;
    const int wn   = tid >> 7;

    const int k4 = (tid & 7) * 4;
    const int mb = tid >> 3;

    const uint32_t* Ag = A  + (size_t)(blockIdx.y*128 + mb)*Kdim + k4;
    const uint32_t* Bg = Bm + (size_t)(blockIdx.x*128 + mb)*Kdim + k4;
    const uint32_t sbase = smem_u32(gsm);

    float acc[2][8][4];
#pragma unroll
    for (int mt = 0; mt < 2; mt++)
#pragma unroll
        for (int nt = 0; nt < 8; nt++)
#pragma unroll
            for (int r = 0; r < 4; r++) acc[mt][nt][r] = 0.f;

    const int NC = Kdim / 32;

    {
        uint32_t da = sbase + (mb*40 + k4)*4;
        uint32_t db = da + 5120*4;
#pragma unroll
        for (int i = 0; i < 4; i++) {
            cp16(da + i*32*40*4, Ag + (size_t)i*32*Kdim);
            cp16(db + i*32*40*4, Bg + (size_t)i*32*Kdim);
        }
        CP_COMMIT();
    }

    for (int c = 0; c < NC; c++) {
        const int st = c & 1;
        if (c + 1 < NC) {
            uint32_t da = sbase + ((st^1)*GSTG + mb*40 + k4)*4;
            uint32_t db = da + 5120*4;
            const int kt = (c+1)*32;
#pragma unroll
            for (int i = 0; i < 4; i++) {
                cp16(da + i*32*40*4, Ag + kt + (size_t)i*32*Kdim);
                cp16(db + i*32*40*4, Bg + kt + (size_t)i*32*Kdim);
            }
            CP_COMMIT();
            CP_WAIT1();
        } else {
            CP_WAIT0();
        }
        __syncthreads();

        const uint32_t* As = gsm + st*GSTG;
        const uint32_t* Bs = As + 5120;
#pragma unroll
        for (int kk = 0; kk < 4; kk++) {
            uint32_t af[2][4];
#pragma unroll
            for (int mt = 0; mt < 2; mt++) {
                const int r = wm*32 + mt*16 + grp;
                uint2 a0 = *(const uint2*)&As[r*40     + kk*8 + 2*tig];
                uint2 a1 = *(const uint2*)&As[(r+8)*40 + kk*8 + 2*tig];
                af[mt][0] = a0.x; af[mt][1] = a1.x;
                af[mt][2] = a0.y; af[mt][3] = a1.y;
            }
#pragma unroll
            for (int nt = 0; nt < 8; nt++) {
                const int r = wn*64 + nt*8 + grp;
                uint2 b = *(const uint2*)&Bs[r*40 + kk*8 + 2*tig];
                uint32_t bf[2] = {b.x, b.y};
                mma16n8k8(acc[0][nt], af[0], bf);
                mma16n8k8(acc[1][nt], af[1], bf);
            }
        }
        __syncthreads();
    }

    if (MODE == 0) {
#pragma unroll
        for (int mt = 0; mt < 2; mt++) {
            const int r0 = blockIdx.y*128 + wm*32 + mt*16 + grp;
#pragma unroll
            for (int nt = 0; nt < 8; nt++) {
                const int n = blockIdx.x*128 + wn*64 + nt*8 + 2*tig;
                *(float2*)(C + (size_t)r0*Ndim + n) =
                    make_float2(acc[mt][nt][0], acc[mt][nt][1]);
                *(float2*)(C + (size_t)(r0+8)*Ndim + n) =
                    make_float2(acc[mt][nt][2], acc[mt][nt][3]);
            }
        }
    } else {
        const int nblk = blockIdx.x*128;
        const int part = nblk >> 11;            // 0:Q 1:K 2:V
        const int hh   = (nblk & 2047) >> 7;
        if (part < 2) {
            uint32_t* base = (part == 0) ? g_q : g_k;
            const float sc = (part == 0) ? SM_SCALE : 1.0f;
#pragma unroll
            for (int mt = 0; mt < 2; mt++) {
#pragma unroll
                for (int rr = 0; rr < 2; rr++) {
                    const int m  = blockIdx.y*128 + wm*32 + mt*16 + grp + rr*8;
                    const int bb = m >> 11;
                    const int ss = m & 2047;
                    uint32_t* row = base + ((((size_t)bb*NHEAD) + hh)*SL + ss)*HD;
#pragma unroll
                    for (int nt = 0; nt < 8; nt++) {
                        const int d = wn*64 + nt*8 + 2*tig;
                        float v0 = fminf(fmaxf(acc[mt][nt][rr*2+0], -CLIPV), CLIPV)*sc;
                        float v1 = fminf(fmaxf(acc[mt][nt][rr*2+1], -CLIPV), CLIPV)*sc;
                        row[perm8(d)]   = f2tf32(v0);
                        row[perm8(d+1)] = f2tf32(v1);
                    }
                }
            }
        } else {
            // V: transposed store, key-permuted column
#pragma unroll
            for (int mt = 0; mt < 2; mt++) {
#pragma unroll
                for (int rr = 0; rr < 2; rr++) {
                    const int m  = blockIdx.y*128 + wm*32 + mt*16 + grp + rr*8;
                    const int bb = m >> 11;
                    const int ss = m & 2047;
                    const int scol = perm8(ss);
                    uint32_t* vb = g_vT + (((size_t)bb*NHEAD + hh)*HD)*SL + scol;
#pragma unroll
                    for (int nt = 0; nt < 8; nt++) {
                        const int d = wn*64 + nt*8 + 2*tig;
                        float v0 = fminf(fmaxf(acc[mt][nt][rr*2+0], -CLIPV), CLIPV);
                        float v1 = fminf(fmaxf(acc[mt][nt][rr*2+1], -CLIPV), CLIPV);
                        vb[(size_t)perm8(d)  *SL] = f2tf32(v0);
                        vb[(size_t)perm8(d+1)*SL] = f2tf32(v1);
                    }
                }
            }
        }
    }
}

// ============================================================================
// Tensor-core flash attention (proven R9 variant): Q in regs, P in regs,
// double-buffered cp.async K+V+BIAS tiles, heavy-qb-first CTA order, occ 1.
// ============================================================================
#define KSTR 136
#define VSTR 72
#define BSTR 68
#define KS_SZ (64*KSTR)
#define VT_SZ (128*VSTR)
#define BS_SZ (128*BSTR)
#define ATT_U32 (2*KS_SZ + 2*VT_SZ + 2*BS_SZ)
#define ATT_BYTES (ATT_U32*4)

__global__ __launch_bounds__(256, 1)
void attn_mma(const float* __restrict__ bias)
{
    extern __shared__ uint32_t sm[];
    uint32_t* KsB = sm;                         // [2][64][KSTR]
    uint32_t* VtB = sm + 2*KS_SZ;               // [2][128][VSTR]
    float*    BsB = (float*)(sm + 2*KS_SZ + 2*VT_SZ);   // [2][128][BSTR]
    const uint32_t sKs = smem_u32(KsB);
    const uint32_t sVt = smem_u32(VtB);
    const uint32_t sBs = smem_u32(BsB);

    const int qb = (int)gridDim.x - 1 - (int)blockIdx.x;   // heavy first
    const int hh = blockIdx.y;
    const int bb = blockIdx.z;
    const int tid  = threadIdx.x;
    const int w    = tid >> 5;
    const int lane = tid & 31;
    const int grp  = lane >> 2;
    const int tig  = lane & 3;
    const int rbase = w*16;

    const size_t bhs = ((size_t)bb*NHEAD + hh)*SL;
    const uint32_t* Qg = g_q + (bhs + (size_t)qb*128)*HD;
    const uint32_t* Kg = g_k + bhs*HD;
    const uint32_t* Vg = g_vT + bhs*HD;
    const float* biasg = bias + ((size_t)hh*SL + (size_t)qb*128)*SL;

    auto load_tile = [&](int buf, int kb) {
        const uint32_t* Kt = Kg + (size_t)kb*64*HD;
        const uint32_t dK = sKs + buf*KS_SZ*4;
#pragma unroll
        for (int p = 0; p < 8; p++) {
            int i = tid + p*256;
            int r = i >> 5, c4 = (i & 31) << 2;
            cp16(dK + (perm8(r)*KSTR + c4)*4, Kt + (size_t)r*HD + c4);
        }
        const uint32_t* Vt0 = Vg + (size_t)kb*64;
        const uint32_t dV = sVt + buf*VT_SZ*4;
#pragma unroll
        for (int p = 0; p < 8; p++) {
            int i = tid + p*256;
            int d = i >> 4, c4 = (i & 15) << 2;
            cp16(dV + (d*VSTR + c4)*4, Vt0 + (size_t)d*SL + c4);
        }
        const float* Bg0 = biasg + kb*64;
        const uint32_t dB = sBs + buf*BS_SZ*4;
#pragma unroll
        for (int p = 0; p < 8; p++) {
            int i = tid + p*256;
            int r = i >> 4, c4 = (i & 15) << 2;
            cp16(dB + (r*BSTR + c4)*4, Bg0 + (size_t)r*SL + c4);
        }
    };

    load_tile(0, 0);
    CP_COMMIT();

    // Q fragments -> registers (reused across all key tiles)
    uint2 qA[16], qB[16];
    {
        const uint32_t* q0 = Qg + (size_t)(rbase + grp)*HD + 2*tig;
        const uint32_t* q1 = q0 + 8*HD;
#pragma unroll
        for (int kk = 0; kk < 16; kk++) {
            qA[kk] = *(const uint2*)(q0 + kk*8);
            qB[kk] = *(const uint2*)(q1 + kk*8);
        }
    }

    float o[16][4];
#pragma unroll
    for (int nt = 0; nt < 16; nt++)
#pragma unroll
        for (int r = 0; r < 4; r++) o[nt][r] = 0.f;
    float mr0 = -INFINITY, mr1 = -INFINITY, lr0 = 0.f, lr1 = 0.f;

    const int rg0 = qb*128 + rbase + grp;
    const int warp_rmax = qb*128 + rbase + 15;
    const int kb_max = 2*qb + 1;

    for (int kb = 0; kb <= kb_max; kb++) {
        const int buf = kb & 1;
        if (kb < kb_max) {
            load_tile(buf ^ 1, kb + 1);
            CP_COMMIT();
            CP_WAIT1();
        } else {
            CP_WAIT0();
        }
        __syncthreads();

        if (kb*64 <= warp_rmax) {
            const uint32_t* Ks = KsB + buf*KS_SZ;
            const uint32_t* Vt = VtB + buf*VT_SZ;
            const float*    Bt = BsB + buf*BS_SZ;

            // ---- QK^T: m16 x n64, k=128 ----
            float c[8][4];
#pragma unroll
            for (int nt = 0; nt < 8; nt++)
#pragma unroll
                for (int r = 0; r < 4; r++) c[nt][r] = 0.f;

#pragma unroll
            for (int kk = 0; kk < 16; kk++) {
                uint32_t af[4] = {qA[kk].x, qB[kk].x, qA[kk].y, qB[kk].y};
#pragma unroll
                for (int nt = 0; nt < 8; nt++) {
                    uint2 kf = *(const uint2*)&Ks[(nt*8+grp)*KSTR + kk*8 + 2*tig];
                    uint32_t bf[2] = {kf.x, kf.y};
                    mma16n8k8(c[nt], af, bf);
                }
            }

            // ---- bias (smem) + causal + online softmax ----
            const float* b0r = Bt + (rbase+grp)*BSTR;
            const float* b1r = b0r + 8*BSTR;
            float rm0 = -INFINITY, rm1 = -INFINITY;
#pragma unroll
            for (int nt = 0; nt < 8; nt++) {
                const int k0 = nt*8 + tig;
                const int cg = kb*64 + k0;
                c[nt][0] = (cg     > rg0    ) ? -INFINITY : c[nt][0] + b0r[k0];
                c[nt][1] = (cg + 4 > rg0    ) ? -INFINITY : c[nt][1] + b0r[k0+4];
                c[nt][2] = (cg     > rg0 + 8) ? -INFINITY : c[nt][2] + b1r[k0];
                c[nt][3] = (cg + 4 > rg0 + 8) ? -INFINITY : c[nt][3] + b1r[k0+4];
                rm0 = fmaxf(rm0, fmaxf(c[nt][0], c[nt][1]));
                rm1 = fmaxf(rm1, fmaxf(c[nt][2], c[nt][3]));
            }
            rm0 = fmaxf(rm0, __shfl_xor_sync(0xffffffffu, rm0, 1));
            rm0 = fmaxf(rm0, __shfl_xor_sync(0xffffffffu, rm0, 2));
            rm1 = fmaxf(rm1, __shfl_xor_sync(0xffffffffu, rm1, 1));
            rm1 = fmaxf(rm1, __shfl_xor_sync(0xffffffffu, rm1, 2));

            const float mn0 = fmaxf(mr0, rm0);
            const float mn1 = fmaxf(mr1, rm1);
            const float corr0 = __expf(mr0 - mn0);
            const float corr1 = __expf(mr1 - mn1);
            mr0 = mn0; mr1 = mn1;

            float rs0 = 0.f, rs1 = 0.f;
#pragma unroll
            for (int nt = 0; nt < 8; nt++) {
                c[nt][0] = __uint_as_float(f2tf32(__expf(c[nt][0] - mn0)));
                c[nt][1] = __uint_as_float(f2tf32(__expf(c[nt][1] - mn0)));
                c[nt][2] = __uint_as_float(f2tf32(__expf(c[nt][2] - mn1)));
                c[nt][3] = __uint_as_float(f2tf32(__expf(c[nt][3] - mn1)));
                rs0 += c[nt][0] + c[nt][1];
                rs1 += c[nt][2] + c[nt][3];
            }
            rs0 += __shfl_xor_sync(0xffffffffu, rs0, 1);
            rs0 += __shfl_xor_sync(0xffffffffu, rs0, 2);
            rs1 += __shfl_xor_sync(0xffffffffu, rs1, 1);
            rs1 += __shfl_xor_sync(0xffffffffu, rs1, 2);
            lr0 = lr0*corr0 + rs0;
            lr1 = lr1*corr1 + rs1;
#pragma unroll
            for (int nt = 0; nt < 16; nt++) {
                o[nt][0] *= corr0; o[nt][1] *= corr0;
                o[nt][2] *= corr1; o[nt][3] *= corr1;
            }

            // ---- P V: m16 x n128, k=64; A-fragment direct from C-fragment ----
#pragma unroll
            for (int kk = 0; kk < 8; kk++) {
                uint32_t af[4] = {__float_as_uint(c[kk][0]),
                                  __float_as_uint(c[kk][2]),
                                  __float_as_uint(c[kk][1]),
                                  __float_as_uint(c[kk][3])};
#pragma unroll
                for (int nt = 0; nt < 16; nt++) {
                    uint2 vb = *(const uint2*)&Vt[(nt*8+grp)*VSTR + kk*8 + 2*tig];
                    uint32_t bf[2] = {vb.x, vb.y};
                    mma16n8k8(o[nt], af, bf);
                }
            }
        }

        __syncthreads();          // everyone done with buf before it refills
    }

    // epilogue: normalize, tf32, write ctx (slot order matches g_wout_p perm)
    const float inv0 = 1.0f / lr0;
    const float inv1 = 1.0f / lr1;
    uint32_t* dst0 = g_ctx + ((size_t)bb*SL + rg0    )*HDIM + hh*HD;
    uint32_t* dst1 = g_ctx + ((size_t)bb*SL + rg0 + 8)*HDIM + hh*HD;
#pragma unroll
    for (int nt = 0; nt < 16; nt++) {
        const int d = nt*8 + 2*tig;
        *(uint2*)(dst0 + d) = make_uint2(f2tf32(o[nt][0]*inv0),
                                         f2tf32(o[nt][1]*inv0));
        *(uint2*)(dst1 + d) = make_uint2(f2tf32(o[nt][2]*inv1),
                                         f2tf32(o[nt][3]*inv1));
    }
}

// ============================================================================
extern "C" void kernel_launch(void* const* d_in, const int* in_sizes, int n_in,
                              void* d_out, int out_size)
{
    const float* hidden = (const float*)d_in[0];   // [B,S,H]
    const float* bias   = (const float*)d_in[1];   // [NH,S,S]
    // d_in[2] attention_mask: deterministic causal, applied analytically
    const float* Wqkv   = (const float*)d_in[3];   // [3H,H]
    const float* Wout   = (const float*)d_in[4];   // [H,H]
    float* out = (float*)d_out;

    cudaFuncSetAttribute(attn_mma,
                         cudaFuncAttributeMaxDynamicSharedMemorySize, ATT_BYTES);
    cudaFuncSetAttribute(mma_gemm_p<0>,
                         cudaFuncAttributeMaxDynamicSharedMemorySize, GEMM_SMEM_BYTES);
    cudaFuncSetAttribute(mma_gemm_p<1>,
                         cudaFuncAttributeMaxDynamicSharedMemorySize, GEMM_SMEM_BYTES);

    void *hidp, *wqkvp, *woutp, *ctxp;
    cudaGetSymbolAddress(&hidp,  g_hid_p);
    cudaGetSymbolAddress(&wqkvp, g_wqkv_p);
    cudaGetSymbolAddress(&woutp, g_wout_p);
    cudaGetSymbolAddress(&ctxp,  g_ctx);

    // 0) permute + tf32-convert inputs
    prep_perm<<<(MTOT*HDIM/4 + 255)/256, 256>>>(hidden, (uint32_t*)hidp, MTOT*HDIM/4);
    prep_perm<<<(N3H*HDIM/4  + 255)/256, 256>>>(Wqkv,   (uint32_t*)wqkvp, N3H*HDIM/4);
    prep_perm<<<(HDIM*HDIM/4 + 255)/256, 256>>>(Wout,   (uint32_t*)woutp, HDIM*HDIM/4);

    // 1) QKV projection + clamp + scale(Q) + scatter (V transposed)
    mma_gemm_p<1><<<dim3(N3H/128, MTOT/128), 256, GEMM_SMEM_BYTES>>>(
        (const uint32_t*)hidp, (const uint32_t*)wqkvp, nullptr, N3H, HDIM);

    // 2) attention (double-buffered K/V/bias, heavy-first, Q+P in regs)
    attn_mma<<<dim3(SL/128, NHEAD, NB), 256, ATT_BYTES>>>(bias);

    // 3) output projection
    mma_gemm_p<0><<<dim3(HDIM/128, MTOT/128), 256, GEMM_SMEM_BYTES>>>(
        (const uint32_t*)ctxp, (const uint32_t*)woutp, out, HDIM, HDIM);
}